// round 15
// baseline (speedup 1.0000x reference)
#include <cuda_runtime.h>

#define D 8
#define NTOT 1024
#define BX 32
#define BY 4
// NPAIR = 1: each thread computes ONE adjacent m-pair (2 outputs) to halve
// live register state (d2+e = 16 u64) and buy occupancy (28 warps/SM at <=73 regs).

typedef unsigned long long u64;

__device__ __forceinline__ u64 pack2(float lo, float hi) {
    u64 r; asm("mov.b64 %0, {%1,%2};" : "=l"(r) : "f"(lo), "f"(hi)); return r;
}
__device__ __forceinline__ void unpack2(u64 v, float& lo, float& hi) {
    asm("mov.b64 {%0,%1}, %2;" : "=f"(lo), "=f"(hi) : "l"(v));
}
__device__ __forceinline__ u64 fma2(u64 a, u64 b, u64 c) {
    u64 d; asm("fma.rn.f32x2 %0, %1, %2, %3;" : "=l"(d) : "l"(a), "l"(b), "l"(c)); return d;
}
__device__ __forceinline__ u64 mul2(u64 a, u64 b) {
    u64 d; asm("mul.rn.f32x2 %0, %1, %2;" : "=l"(d) : "l"(a), "l"(b)); return d;
}
__device__ __forceinline__ u64 add2(u64 a, u64 b) {
    u64 d; asm("add.rn.f32x2 %0, %1, %2;" : "=l"(d) : "l"(a), "l"(b)); return d;
}
__device__ __forceinline__ float ex2f(float x) {
    float r; asm("ex2.approx.ftz.f32 %0, %1;" : "=f"(r) : "f"(x)); return r;
}
__device__ __forceinline__ float frcp(float x) {
    float r; asm("rcp.approx.ftz.f32 %0, %1;" : "=f"(r) : "f"(x)); return r;
}
__device__ __forceinline__ u64 lo4(float4 v) { return pack2(v.x, v.y); }
__device__ __forceinline__ u64 hi4(float4 v) { return pack2(v.z, v.w); }

__global__ __launch_bounds__(BX * BY, 7)
void taylor_rbf_fused(const float* __restrict__ x1,
                      const float* __restrict__ x2,
                      const float* __restrict__ L,
                      const float* __restrict__ sigma,
                      float* __restrict__ out) {
    __shared__ float4 sABAn[D][D];  // [j][c] = {AB,AB,An,An}; AB=s0*cf_j*M, An=-s0*cf_j*M^2
    __shared__ float4 sI4[32];      // [a*4+kp]: inv2[a][k] * (-0.5*log2 e), dup pairs
    __shared__ float4 sQ4[D];       // [d]: {q0,q0,q1,q1}  q0=2*s0*cf, q1=-4*s0*cf*tl
    __shared__ float2 sLJ[D];       // lij2_j (duplicated)
    __shared__ float2 sx2[D][BX];   // [k][t] = (x2[m0+2t], x2[m0+2t+1])

    const int tx = threadIdx.x, ty = threadIdx.y;
    const int tid = ty * BX + tx;

    // ---- per-block constant precompute (first 64 threads cover all (c,j)) ----
    if (tid < 64) {
        const int c = tid >> 3, j = tid & 7;
        float s0  = sigma[0];
        float Ljc = L[j * D + c];
        float L0c = L[c];
        float i0c = frcp(L0c * L0c);
        float ijc = frcp(Ljc * Ljc);
        float M   = i0c + ijc;
        float l0j = L[j];
        float lij2 = l0j * l0j;
        float cf  = s0 * sigma[j] * frcp(lij2 * lij2);
        float AB  = cf * M;
        float An  = -AB * M;
        sABAn[j][c] = make_float4(AB, AB, An, An);
        // exp table, reusing (a,k) = (c,j)
        float Lak = L[c * D + j];
        float v = -0.72134752044448170368f * frcp(Lak * Lak);
        const int fi = c * 16 + (j >> 1) * 4 + (j & 1) * 2;
        float* pI = (float*)sI4; pI[fi] = v; pI[fi + 1] = v;
    } else if (tid < 72) {
        const int d = tid - 64;
        float s0  = sigma[0];
        float l0d = L[d];
        float lj2 = l0d * l0d;
        float Ldd = L[d * D + d];
        float idd = frcp(Ldd * Ldd);
        float i0d = frcp(lj2);
        float tl  = i0d + idd;
        float cfd = s0 * sigma[d] * frcp(lj2 * lj2);
        sQ4[d] = make_float4(2.0f * cfd, 2.0f * cfd, -4.0f * cfd * tl, -4.0f * cfd * tl);
        sLJ[d] = make_float2(lj2, lj2);
    }

    // ---- stage x2 tile: 64 m rows, adjacent (m, m+1) packed per float2 ----
    const int m0 = blockIdx.x * (BX * 2);   // 64 m per block
    for (int i = tid; i < BX * 2 * D; i += BX * BY) {
        const int r = i / D;           // local row 0..63
        const int k = i - r * D;
        ((float*)&sx2[k][r >> 1])[r & 1] = x2[(m0 + r) * D + k];
    }

    const int n = blockIdx.y * BY + ty;
    float a1s[D];
    #pragma unroll
    for (int k = 0; k < D; k++) a1s[k] = x1[n * D + k];

    __syncthreads();

    const u64 NEG1 = pack2(-1.0f, -1.0f);

    // diff^2 for the adjacent m-pair
    u64 d2[D];
    #pragma unroll
    for (int k = 0; k < D; k++) {
        u64 a1 = pack2(a1s[k], a1s[k]);
        u64 xp = *(const u64*)&sx2[k][tx];
        u64 dd = fma2(xp, NEG1, a1);
        d2[k] = mul2(dd, dd);
    }

    // e[a] = exp(-0.5 * <d2, inv2[a,:]>) via pre-scaled rows + ex2
    u64 e[D];
    #pragma unroll
    for (int a = 0; a < D; a++) {
        float4 q0 = sI4[a * 4 + 0];
        float4 q1 = sI4[a * 4 + 1];
        float4 q2 = sI4[a * 4 + 2];
        float4 q3 = sI4[a * 4 + 3];
        u64 s0 = mul2(d2[0], lo4(q0));
        u64 s1 = mul2(d2[1], hi4(q0));
        s0 = fma2(d2[2], lo4(q1), s0);
        s1 = fma2(d2[3], hi4(q1), s1);
        s0 = fma2(d2[4], lo4(q2), s0);
        s1 = fma2(d2[5], hi4(q2), s1);
        s0 = fma2(d2[6], lo4(q3), s0);
        s1 = fma2(d2[7], hi4(q3), s1);
        u64 s = add2(s0, s1);
        float lo, hi; unpack2(s, lo, hi);
        e[a] = pack2(ex2f(lo), ex2f(hi));
    }

    u64 tot = pack2(0.f, 0.f);

    // one pass over j: double-sum + collapsed diagonal correction, fused epilogue
    #pragma unroll
    for (int j = 0; j < D; j++) {
        u64 in0 = pack2(0.f, 0.f), in1 = pack2(0.f, 0.f);
        #pragma unroll
        for (int cp = 0; cp < 4; cp++) {
            const int c0 = 2 * cp, c1 = 2 * cp + 1;
            float4 q0 = sABAn[j][c0];
            float4 q1 = sABAn[j][c1];
            u64 t0 = fma2(hi4(q0), d2[c0], lo4(q0));   // AB - A*d2
            in0 = fma2(t0, e[c0], in0);
            u64 t1 = fma2(hi4(q1), d2[c1], lo4(q1));
            in1 = fma2(t1, e[c1], in1);
        }
        u64 ljp = *(const u64*)&sLJ[j];
        float4 qd = sQ4[j];
        u64 ej = e[j];
        u64 dd = d2[j];
        // fused: tot += [ (in0+in1)*(lj-dd) + (q0+q1*dd)*ej ] * ej
        u64 inn = add2(in0, in1);
        u64 w   = fma2(dd, NEG1, ljp);
        u64 t   = mul2(inn, w);
        u64 cor = fma2(hi4(qd), dd, lo4(qd));
        u64 t2  = fma2(cor, ej, t);
        tot     = fma2(t2, ej, tot);
    }

    u64 r = mul2(tot, e[0]);
    *(u64*)(out + n * NTOT + m0 + 2 * tx) = r;   // coalesced STG.64, adjacent m-pair

}

extern "C" void kernel_launch(void* const* d_in, const int* in_sizes, int n_in,
                              void* d_out, int out_size) {
    const float* x1    = (const float*)d_in[0];
    const float* x2    = (const float*)d_in[1];
    const float* L     = (const float*)d_in[2];
    const float* sigma = (const float*)d_in[3];
    float* out = (float*)d_out;

    dim3 block(BX, BY);
    dim3 grid(NTOT / (BX * 2), NTOT / BY);   // (16, 256)
    taylor_rbf_fused<<<grid, block>>>(x1, x2, L, sigma, out);
}